// round 1
// baseline (speedup 1.0000x reference)
#include <cuda_runtime.h>
#include <cuda_fp16.h>
#include <mma.h>

using namespace nvcuda;

// Problem dims
#define TT 512
#define BB 64
#define HH 512
#define G4 2048   // 4*H
#define LL 2

// Decomposition
#define HS 8                  // hidden units per CTA
#define MROWS 32              // 4*HS gate rows per CTA
#define KC 128                // K staging chunk
#define NCTA_PER_LAYER 64
#define NCTA 128
#define NTHREADS 256

// SMEM leading dims (padded for conflict-free ldmatrix)
#define LDW 520               // 512+8 halfs
#define LDU 136               // 128+8 halfs
#define LDG 68                // 64+4 floats

#define OUT_ELEMS (TT*BB*HH)
#define HT_OFF OUT_ELEMS
#define CT_OFF (OUT_ELEMS + LL*BB*HH)

#define SMEM_BYTES (4*MROWS*LDW*2 + 4*BB*LDU*2 + (MROWS*LDG + HS*BB + MROWS)*4)

// 64 MB scratch: layer-0 hidden history h0[t][b][h]
__device__ float g_h0[(size_t)TT * BB * HH];
__device__ unsigned g_bar_count = 0;
__device__ volatile unsigned g_bar_sense = 0;

__device__ __forceinline__ float sigf(float x) { return 1.0f / (1.0f + expf(-x)); }

__global__ void __launch_bounds__(NTHREADS, 1)
lstm_persistent_kernel(const float* __restrict__ x,
                       const float* __restrict__ Wxh,
                       const float* __restrict__ Whh,
                       const float* __restrict__ bxh,
                       const float* __restrict__ bhh,
                       float* __restrict__ out)
{
    const int cta   = blockIdx.x;
    const int layer = cta / NCTA_PER_LAYER;   // 0 or 1
    const int cil   = cta % NCTA_PER_LAYER;
    const int j0    = cil * HS;               // first hidden unit owned
    const int tid   = threadIdx.x;
    const int wid   = tid >> 5;

    extern __shared__ char smem_raw[];
    half* wx_hi = (half*)smem_raw;                    // [MROWS][LDW]
    half* wx_lo = wx_hi + MROWS * LDW;
    half* wh_hi = wx_lo + MROWS * LDW;
    half* wh_lo = wh_hi + MROWS * LDW;
    half* u_hi  = wh_lo + MROWS * LDW;                // [BB][LDU]
    half* u_lo  = u_hi + BB * LDU;
    half* v_hi  = u_lo + BB * LDU;
    half* v_lo  = v_hi + BB * LDU;
    float* gates_s = (float*)(v_lo + BB * LDU);       // [MROWS][LDG]
    float* c_s     = gates_s + MROWS * LDG;           // [HS][BB]
    float* bias_s  = c_s + HS * BB;                   // [MROWS]

    // Replay-safe barrier phase: read current global sense before any barrier.
    unsigned sense = g_bar_sense;

    // ---- Preamble: split weights into fp16 hi/lo in SMEM (held whole kernel) ----
    const float* WxL = Wxh + (size_t)layer * G4 * HH;
    const float* WhL = Whh + (size_t)layer * G4 * HH;
    for (int i = tid; i < MROWS * HH; i += NTHREADS) {
        int rl = i >> 9;            // local row 0..31  (9 = log2(HH))
        int k  = i & (HH - 1);
        int grow = (rl >> 3) * HH + j0 + (rl & 7);   // gate*H + hidden index
        float wx = WxL[(size_t)grow * HH + k];
        half hx = __float2half_rn(wx);
        wx_hi[rl * LDW + k] = hx;
        wx_lo[rl * LDW + k] = __float2half_rn(wx - __half2float(hx));
        float wh = WhL[(size_t)grow * HH + k];
        half hh2 = __float2half_rn(wh);
        wh_hi[rl * LDW + k] = hh2;
        wh_lo[rl * LDW + k] = __float2half_rn(wh - __half2float(hh2));
    }
    if (tid < MROWS) {
        int grow = (tid >> 3) * HH + j0 + (tid & 7);
        bias_s[tid] = bxh[layer * G4 + grow] + bhh[layer * G4 + grow];
    }
    for (int i = tid; i < HS * BB; i += NTHREADS) c_s[i] = 0.0f;
    __syncthreads();

    const int m0 = (wid >> 2) * 16;   // warp's gate-row tile
    const int n0 = (wid & 3) * 16;    // warp's batch tile

    // ---- Pipelined recurrence: superstep s computes layer0 t=s, layer1 t=s-1 ----
    for (int s = 0; s <= TT; ++s) {
        const float* u_src;
        const float* v_src;
        int t;
        bool active;
        if (layer == 0) {
            t = s; active = (s < TT);
            u_src = x + (size_t)t * BB * HH;
            v_src = (t > 0) ? (g_h0 + (size_t)(t - 1) * BB * HH) : nullptr;
        } else {
            t = s - 1; active = (s >= 1);
            u_src = g_h0 + (size_t)t * BB * HH;
            v_src = (t > 0) ? (out + (size_t)(t - 1) * BB * HH) : nullptr;
        }

        if (active) {
            wmma::fragment<wmma::accumulator, 16, 16, 16, float> acc;
            wmma::fill_fragment(acc, 0.0f);

            for (int kc = 0; kc < HH; kc += KC) {
                __syncthreads();  // staging buffers free from previous chunk
                // Stage u chunk: [BB][KC] fp32 -> hi/lo fp16
                for (int i = tid; i < BB * (KC / 4); i += NTHREADS) {
                    int row = i >> 5;       // 32 float4 per row
                    int c4  = i & 31;
                    float4 vv = *(const float4*)(u_src + (size_t)row * HH + kc + c4 * 4);
                    int base = row * LDU + c4 * 4;
                    half hx;
                    hx = __float2half_rn(vv.x); u_hi[base+0] = hx; u_lo[base+0] = __float2half_rn(vv.x - __half2float(hx));
                    hx = __float2half_rn(vv.y); u_hi[base+1] = hx; u_lo[base+1] = __float2half_rn(vv.y - __half2float(hx));
                    hx = __float2half_rn(vv.z); u_hi[base+2] = hx; u_lo[base+2] = __float2half_rn(vv.z - __half2float(hx));
                    hx = __float2half_rn(vv.w); u_hi[base+3] = hx; u_lo[base+3] = __float2half_rn(vv.w - __half2float(hx));
                }
                if (v_src) {
                    for (int i = tid; i < BB * (KC / 4); i += NTHREADS) {
                        int row = i >> 5;
                        int c4  = i & 31;
                        float4 vv = *(const float4*)(v_src + (size_t)row * HH + kc + c4 * 4);
                        int base = row * LDU + c4 * 4;
                        half hx;
                        hx = __float2half_rn(vv.x); v_hi[base+0] = hx; v_lo[base+0] = __float2half_rn(vv.x - __half2float(hx));
                        hx = __float2half_rn(vv.y); v_hi[base+1] = hx; v_lo[base+1] = __float2half_rn(vv.y - __half2float(hx));
                        hx = __float2half_rn(vv.z); v_hi[base+2] = hx; v_lo[base+2] = __float2half_rn(vv.z - __half2float(hx));
                        hx = __float2half_rn(vv.w); v_hi[base+3] = hx; v_lo[base+3] = __float2half_rn(vv.w - __half2float(hx));
                    }
                }
                __syncthreads();

                for (int kk = 0; kk < KC; kk += 16) {
                    wmma::fragment<wmma::matrix_a, 16, 16, 16, half, wmma::row_major> a_hi, a_lo;
                    wmma::fragment<wmma::matrix_b, 16, 16, 16, half, wmma::col_major> b_hi, b_lo;
                    // input-projection GEMM (Wx @ u^T), 3-term fp16 split
                    wmma::load_matrix_sync(a_hi, wx_hi + m0 * LDW + kc + kk, LDW);
                    wmma::load_matrix_sync(a_lo, wx_lo + m0 * LDW + kc + kk, LDW);
                    wmma::load_matrix_sync(b_hi, u_hi + n0 * LDU + kk, LDU);
                    wmma::load_matrix_sync(b_lo, u_lo + n0 * LDU + kk, LDU);
                    wmma::mma_sync(acc, a_hi, b_hi, acc);
                    wmma::mma_sync(acc, a_hi, b_lo, acc);
                    wmma::mma_sync(acc, a_lo, b_hi, acc);
                    if (v_src) {
                        // recurrent GEMM (Wh @ h^T)
                        wmma::load_matrix_sync(a_hi, wh_hi + m0 * LDW + kc + kk, LDW);
                        wmma::load_matrix_sync(a_lo, wh_lo + m0 * LDW + kc + kk, LDW);
                        wmma::load_matrix_sync(b_hi, v_hi + n0 * LDU + kk, LDU);
                        wmma::load_matrix_sync(b_lo, v_lo + n0 * LDU + kk, LDU);
                        wmma::mma_sync(acc, a_hi, b_hi, acc);
                        wmma::mma_sync(acc, a_hi, b_lo, acc);
                        wmma::mma_sync(acc, a_lo, b_hi, acc);
                    }
                }
            }
            wmma::store_matrix_sync(gates_s + m0 * LDG + n0, acc, LDG, wmma::mem_row_major);
            __syncthreads();

            // Cell update for this CTA's HS hidden units x 64 batches
            float* dsth = (layer == 0) ? (g_h0 + (size_t)t * BB * HH)
                                       : (out + (size_t)t * BB * HH);
            for (int idx = tid; idx < HS * BB; idx += NTHREADS) {
                int j = idx >> 6;
                int b = idx & 63;
                float ig = gates_s[(j)      * LDG + b] + bias_s[j];
                float fg = gates_s[(8 + j)  * LDG + b] + bias_s[8 + j];
                float gg = gates_s[(16 + j) * LDG + b] + bias_s[16 + j];
                float og = gates_s[(24 + j) * LDG + b] + bias_s[24 + j];
                float cold = c_s[idx];
                float cn = sigf(fg) * cold + sigf(ig) * tanhf(gg);
                c_s[idx] = cn;
                dsth[(size_t)b * HH + j0 + j] = sigf(og) * tanhf(cn);
            }
        }

        // ---- grid-wide sense-reversing barrier (publishes h writes) ----
        __threadfence();
        __syncthreads();
        if (tid == 0) {
            sense ^= 1u;
            unsigned old = atomicAdd(&g_bar_count, 1u);
            if (old == NCTA - 1) {
                g_bar_count = 0;
                __threadfence();
                g_bar_sense = sense;
            } else {
                while (g_bar_sense != sense) { }
            }
            __threadfence();
        }
        __syncthreads();
    }

    // ---- Tail: final (hT, cT) per layer ----
    const float* hsrc = (layer == 0) ? (g_h0 + (size_t)(TT - 1) * BB * HH)
                                     : (out + (size_t)(TT - 1) * BB * HH);
    float* hT = out + HT_OFF + (size_t)layer * BB * HH;
    float* cT = out + CT_OFF + (size_t)layer * BB * HH;
    for (int idx = tid; idx < HS * BB; idx += NTHREADS) {
        int j = idx >> 6;
        int b = idx & 63;
        hT[(size_t)b * HH + j0 + j] = hsrc[(size_t)b * HH + j0 + j];
        cT[(size_t)b * HH + j0 + j] = c_s[idx];
    }
}

extern "C" void kernel_launch(void* const* d_in, const int* in_sizes, int n_in,
                              void* d_out, int out_size) {
    const float* x   = (const float*)d_in[0];
    const float* Wxh = (const float*)d_in[1];
    const float* Whh = (const float*)d_in[2];
    const float* bxh = (const float*)d_in[3];
    const float* bhh = (const float*)d_in[4];
    float* out = (float*)d_out;

    cudaFuncSetAttribute(lstm_persistent_kernel,
                         cudaFuncAttributeMaxDynamicSharedMemorySize, SMEM_BYTES);
    lstm_persistent_kernel<<<NCTA, NTHREADS, SMEM_BYTES>>>(x, Wxh, Whh, bxh, bhh, out);
}

// round 5
// speedup vs baseline: 1.1275x; 1.1275x over previous
#include <cuda_runtime.h>
#include <cuda_fp16.h>
#include <mma.h>
#include <cuda_pipeline.h>

using namespace nvcuda;

// Problem dims
#define TT 512
#define BB 64
#define HH 512
#define G4 2048
#define LL 2
#define NBH (BB*HH)           // 32768

// Decomposition
#define HS 8                  // hidden units per CTA
#define MROWS 32              // 4*HS gate rows per CTA
#define KC 32                 // K chunk
#define NCHUNK (HH/KC)        // 16
#define NSTAGE 3
#define NCTA_PER_LAYER 64
#define NCTA 128
#define NTHREADS 512

// SMEM leading dims (halfs / floats)
#define LDW 520               // 512+8
#define LDU 40                // 32+8  (80B row stride, conflict-free ldmatrix)
#define LDG 68

#define WPLANE (MROWS*LDW)    // 16640 halfs
#define UPLANE (BB*LDU)       // 2560 halfs
#define STAGEH (4*UPLANE)     // one stage: u_hi,u_lo,v_hi,v_lo

#define OUT_ELEMS (TT*BB*HH)
#define HT_OFF OUT_ELEMS
#define CT_OFF (OUT_ELEMS + LL*BB*HH)

#define SMEM_HALFS (4*WPLANE + NSTAGE*STAGEH)
#define SMEM_FLOATS (2*MROWS*LDG + HS*BB + MROWS)
#define SMEM_BYTES (SMEM_HALFS*2 + SMEM_FLOATS*4)

// Global transport planes (fp16 hi/lo split), ~200MB static scratch
__device__ half g_x_hi[(size_t)TT*NBH], g_x_lo[(size_t)TT*NBH];
__device__ half g_h0_hi[(size_t)TT*NBH], g_h0_lo[(size_t)TT*NBH];
__device__ half g_h1_hi[(size_t)TT*NBH], g_h1_lo[(size_t)TT*NBH];

// Sync state (reset by reset kernel each launch)
__device__ unsigned g_bar_count[2];
__device__ volatile int g_bar_sense[2];   // monotonic: last completed step+1
__device__ unsigned g_gbar_count;
__device__ volatile int g_gbar_sense;

__global__ void reset_kernel() {
    g_bar_count[0] = 0; g_bar_count[1] = 0;
    g_bar_sense[0] = 0; g_bar_sense[1] = 0;
    g_gbar_count = 0;   g_gbar_sense = 0;
}

__device__ __forceinline__ float sigf(float x) { return 1.0f / (1.0f + expf(-x)); }

__global__ void __launch_bounds__(NTHREADS, 1)
lstm_persistent_kernel(const float* __restrict__ x,
                       const float* __restrict__ Wxh,
                       const float* __restrict__ Whh,
                       const float* __restrict__ bxh,
                       const float* __restrict__ bhh,
                       float* __restrict__ out)
{
    const int cta   = blockIdx.x;
    const int layer = cta / NCTA_PER_LAYER;
    const int cil   = cta % NCTA_PER_LAYER;
    const int j0    = cil * HS;
    const int tid   = threadIdx.x;
    const int wid   = tid >> 5;

    extern __shared__ char smem_raw[];
    half* wx_hi = (half*)smem_raw;
    half* wx_lo = wx_hi + WPLANE;
    half* wh_hi = wx_lo + WPLANE;
    half* wh_lo = wh_hi + WPLANE;
    half* stage = wh_lo + WPLANE;                       // NSTAGE * STAGEH halfs
    float* gates_x = (float*)(stage + NSTAGE*STAGEH);   // [MROWS][LDG]
    float* gates_h = gates_x + MROWS*LDG;
    float* c_s     = gates_h + MROWS*LDG;               // [HS*BB]
    float* bias_s  = c_s + HS*BB;                       // [MROWS]

    // ---- Preamble: split this layer's weight rows into fp16 hi/lo (resident) ----
    const float* WxL = Wxh + (size_t)layer * G4 * HH;
    const float* WhL = Whh + (size_t)layer * G4 * HH;
    for (int i = tid; i < MROWS * HH; i += NTHREADS) {
        int rl = i >> 9;
        int k  = i & (HH - 1);
        int grow = (rl >> 3) * HH + j0 + (rl & 7);
        float wx = WxL[(size_t)grow * HH + k];
        half hx = __float2half_rn(wx);
        wx_hi[rl * LDW + k] = hx;
        wx_lo[rl * LDW + k] = __float2half_rn(wx - __half2float(hx));
        float wh = WhL[(size_t)grow * HH + k];
        half hh2 = __float2half_rn(wh);
        wh_hi[rl * LDW + k] = hh2;
        wh_lo[rl * LDW + k] = __float2half_rn(wh - __half2float(hh2));
    }
    if (tid < MROWS) {
        int grow = (tid >> 3) * HH + j0 + (tid & 7);
        bias_s[tid] = bxh[layer * G4 + grow] + bhh[layer * G4 + grow];
    }
    c_s[tid] = 0.0f;

    // ---- Phase 0: convert x to hi/lo planes once (all CTAs cooperate) ----
    {
        const float4* x4 = (const float4*)x;
        size_t total4 = (size_t)TT * NBH / 4;
        for (size_t i = (size_t)cta * NTHREADS + tid; i < total4; i += (size_t)NCTA * NTHREADS) {
            float4 v = x4[i];
            half a0 = __float2half_rn(v.x), a1 = __float2half_rn(v.y);
            half a2 = __float2half_rn(v.z), a3 = __float2half_rn(v.w);
            half b0 = __float2half_rn(v.x - __half2float(a0));
            half b1 = __float2half_rn(v.y - __half2float(a1));
            half b2 = __float2half_rn(v.z - __half2float(a2));
            half b3 = __float2half_rn(v.w - __half2float(a3));
            ((half2*)g_x_hi)[i*2]   = __halves2half2(a0, a1);
            ((half2*)g_x_hi)[i*2+1] = __halves2half2(a2, a3);
            ((half2*)g_x_lo)[i*2]   = __halves2half2(b0, b1);
            ((half2*)g_x_lo)[i*2+1] = __halves2half2(b2, b3);
        }
    }
    // one-shot global barrier
    __threadfence();
    __syncthreads();
    if (tid == 0) {
        unsigned old = atomicAdd(&g_gbar_count, 1u);
        if (old == NCTA - 1) { __threadfence(); g_gbar_sense = 1; }
        else { while (g_gbar_sense < 1) { } }
    }
    __syncthreads();

    const int wgrp = (wid < 8) ? 0 : 1;     // 0: x-side GEMM, 1: h-side GEMM
    const int wl   = wid & 7;
    const int m0   = (wl >> 2) * 16;
    const int n0   = (wl & 3) * 16;
    const half* A_hi = wgrp ? wh_hi : wx_hi;
    const half* A_lo = wgrp ? wh_lo : wx_lo;
    const int sOff   = wgrp ? 2*UPLANE : 0;

    // ---- Recurrence ----
    for (int t = 0; t < TT; ++t) {
        const bool has_v = (t > 0);
        const size_t uoff = (size_t)t * NBH;
        const size_t voff = (size_t)(t - 1) * NBH;
        const half *uh, *ul, *vh, *vl;
        if (layer == 0) {
            uh = g_x_hi + uoff;  ul = g_x_lo + uoff;
            vh = g_h0_hi + voff; vl = g_h0_lo + voff;
        } else {
            uh = g_h0_hi + uoff; ul = g_h0_lo + uoff;
            vh = g_h1_hi + voff; vl = g_h1_lo + voff;
        }

        // layer 1 waits for layer 0 to publish h0[t]
        if (layer == 1) {
            if (tid == 0) { while (g_bar_sense[0] < t + 1) { } }
            __syncthreads();
            __threadfence();
        }

        const half* psrc[4] = { uh, ul, vh, vl };
        const int nops = (has_v ? 4 : 2) * 256;     // 256 x 16B ops per plane

        // prologue: issue chunks 0,1
        #pragma unroll
        for (int pc = 0; pc < 2; ++pc) {
            for (int i = tid; i < nops; i += NTHREADS) {
                int plane = i >> 8, r = (i >> 2) & 63, s = i & 3;
                __pipeline_memcpy_async(
                    stage + pc*STAGEH + plane*UPLANE + r*LDU + s*8,
                    psrc[plane] + (size_t)r*HH + pc*KC + s*8, 16);
            }
            __pipeline_commit();
        }

        wmma::fragment<wmma::accumulator, 16, 16, 16, float> acc0, acc1, acc2;
        wmma::fill_fragment(acc0, 0.0f);
        wmma::fill_fragment(acc1, 0.0f);
        wmma::fill_fragment(acc2, 0.0f);
        const bool mywork = (wgrp == 0) || has_v;

        for (int c = 0; c < NCHUNK; ++c) {
            __pipeline_wait_prior(1);
            __syncthreads();
            if (mywork) {
                const half* bbase = stage + (c % NSTAGE)*STAGEH + sOff;
                #pragma unroll
                for (int kk = 0; kk < KC; kk += 16) {
                    wmma::fragment<wmma::matrix_a, 16, 16, 16, half, wmma::row_major> a_hi, a_lo;
                    wmma::fragment<wmma::matrix_b, 16, 16, 16, half, wmma::col_major> b_hi, b_lo;
                    wmma::load_matrix_sync(a_hi, A_hi + m0*LDW + c*KC + kk, LDW);
                    wmma::load_matrix_sync(a_lo, A_lo + m0*LDW + c*KC + kk, LDW);
                    wmma::load_matrix_sync(b_hi, bbase + n0*LDU + kk, LDU);
                    wmma::load_matrix_sync(b_lo, bbase + UPLANE + n0*LDU + kk, LDU);
                    wmma::mma_sync(acc0, a_hi, b_hi, acc0);
                    wmma::mma_sync(acc1, a_hi, b_lo, acc1);
                    wmma::mma_sync(acc2, a_lo, b_hi, acc2);
                }
            }
            if (c + 2 < NCHUNK) {
                int nc = c + 2;
                for (int i = tid; i < nops; i += NTHREADS) {
                    int plane = i >> 8, r = (i >> 2) & 63, s = i & 3;
                    __pipeline_memcpy_async(
                        stage + (nc % NSTAGE)*STAGEH + plane*UPLANE + r*LDU + s*8,
                        psrc[plane] + (size_t)r*HH + nc*KC + s*8, 16);
                }
            }
            __pipeline_commit();
        }

        #pragma unroll
        for (int e = 0; e < acc0.num_elements; ++e)
            acc0.x[e] += acc1.x[e] + acc2.x[e];
        float* gbuf = (wgrp == 0) ? gates_x : gates_h;
        wmma::store_matrix_sync(gbuf + m0*LDG + n0, acc0, LDG, wmma::mem_row_major);
        __syncthreads();

        // ---- cell update: one (hidden j, batch b) per thread ----
        {
            int j = tid >> 6;
            int b = tid & 63;
            float ig = gates_x[(j)      * LDG + b] + gates_h[(j)      * LDG + b] + bias_s[j];
            float fg = gates_x[(8 + j)  * LDG + b] + gates_h[(8 + j)  * LDG + b] + bias_s[8 + j];
            float gg = gates_x[(16 + j) * LDG + b] + gates_h[(16 + j) * LDG + b] + bias_s[16 + j];
            float og = gates_x[(24 + j) * LDG + b] + gates_h[(24 + j) * LDG + b] + bias_s[24 + j];
            float cold = c_s[tid];
            float cn = sigf(fg) * cold + sigf(ig) * tanhf(gg);
            c_s[tid] = cn;
            float hv = sigf(og) * tanhf(cn);
            half hhv = __float2half_rn(hv);
            half hlv = __float2half_rn(hv - __half2float(hhv));
            size_t off = (size_t)t * NBH + (size_t)b * HH + j0 + j;
            if (layer == 0) {
                g_h0_hi[off] = hhv; g_h0_lo[off] = hlv;
                if (t == TT - 1) out[HT_OFF + (size_t)b * HH + j0 + j] = hv;
            } else {
                out[off] = hv;
                g_h1_hi[off] = hhv; g_h1_lo[off] = hlv;
                if (t == TT - 1) out[HT_OFF + NBH + (size_t)b * HH + j0 + j] = hv;
            }
        }

        // ---- per-layer 64-CTA barrier; publishes monotonic epoch t+1 ----
        __threadfence();
        __syncthreads();
        if (tid == 0) {
            unsigned old = atomicAdd(&g_bar_count[layer], 1u);
            if (old == NCTA_PER_LAYER - 1) {
                g_bar_count[layer] = 0;
                __threadfence();
                g_bar_sense[layer] = t + 1;
            } else {
                while (g_bar_sense[layer] < t + 1) { }
            }
        }
        __syncthreads();
    }

    // ---- Tail: cT ----
    {
        int j = tid >> 6;
        int b = tid & 63;
        out[CT_OFF + (size_t)layer * NBH + (size_t)b * HH + j0 + j] = c_s[tid];
    }
}

extern "C" void kernel_launch(void* const* d_in, const int* in_sizes, int n_in,
                              void* d_out, int out_size) {
    const float* x   = (const float*)d_in[0];
    const float* Wxh = (const float*)d_in[1];
    const float* Whh = (const float*)d_in[2];
    const float* bxh = (const float*)d_in[3];
    const float* bhh = (const float*)d_in[4];
    float* out = (float*)d_out;

    reset_kernel<<<1, 1>>>();
    cudaFuncSetAttribute(lstm_persistent_kernel,
                         cudaFuncAttributeMaxDynamicSharedMemorySize, SMEM_BYTES);
    lstm_persistent_kernel<<<NCTA, NTHREADS, SMEM_BYTES>>>(x, Wxh, Whh, bxh, bhh, out);
}

// round 8
// speedup vs baseline: 1.1552x; 1.0246x over previous
#include <cuda_runtime.h>
#include <cuda_fp16.h>
#include <mma.h>
#include <cuda_pipeline.h>

using namespace nvcuda;

// Problem dims
#define TT 512
#define BB 64
#define HH 512
#define G4 2048
#define LL 2
#define NBH (BB*HH)           // 32768

// Decomposition
#define HS 8                  // hidden units per CTA
#define MROWS 32              // 4*HS gate rows per CTA
#define KC 64                 // K chunk
#define NCHUNK (HH/KC)        // 8
#define NSTAGE 2
#define NCTA_PER_LAYER 64
#define NCTA 128
#define NTHREADS 512

// SMEM leading dims (halfs / floats)
#define LDW 520               // 512+8
#define LDU 72                // 64+8 (144B row stride, conflict-free ldmatrix)
#define LDG 68

#define WPLANE (MROWS*LDW)    // 16640 halfs
#define UPLANE (BB*LDU)       // 4608 halfs
#define STAGEH (4*UPLANE)     // one stage: u_hi,u_lo,v_hi,v_lo = 18432 halfs

#define OUT_ELEMS (TT*BB*HH)
#define HT_OFF OUT_ELEMS
#define CT_OFF (OUT_ELEMS + LL*BB*HH)

#define SMEM_HALFS (4*WPLANE + NSTAGE*STAGEH)
#define SMEM_FLOATS (2*MROWS*LDG + HS*BB + MROWS)
#define SMEM_BYTES (SMEM_HALFS*2 + SMEM_FLOATS*4)   // 226432 B

// Global transport planes (fp16 hi/lo split)
__device__ half g_x_hi[(size_t)TT*NBH], g_x_lo[(size_t)TT*NBH];
__device__ half g_h0_hi[(size_t)TT*NBH], g_h0_lo[(size_t)TT*NBH];
__device__ half g_h1_hi[(size_t)TT*NBH], g_h1_lo[(size_t)TT*NBH];

// Sync state, padded so the two layers use distinct 128B lines
__device__ unsigned g_cnt[64];            // [layer*32]
__device__ volatile int g_sns[64];        // [layer*32] monotonic epoch
__device__ unsigned g_gbar_count;
__device__ volatile int g_gbar_sense;

__global__ void reset_kernel() {
    g_cnt[0] = 0; g_cnt[32] = 0;
    g_sns[0] = 0; g_sns[32] = 0;
    g_gbar_count = 0; g_gbar_sense = 0;
}

__device__ __forceinline__ float sigf(float x) { return 1.0f / (1.0f + expf(-x)); }

__global__ void __launch_bounds__(NTHREADS, 1)
lstm_persistent_kernel(const float* __restrict__ x,
                       const float* __restrict__ Wxh,
                       const float* __restrict__ Whh,
                       const float* __restrict__ bxh,
                       const float* __restrict__ bhh,
                       float* __restrict__ out)
{
    const int cta   = blockIdx.x;
    const int layer = cta / NCTA_PER_LAYER;
    const int cil   = cta % NCTA_PER_LAYER;
    const int j0    = cil * HS;
    const int tid   = threadIdx.x;
    const int wid   = tid >> 5;

    extern __shared__ char smem_raw[];
    half* wx_hi = (half*)smem_raw;
    half* wx_lo = wx_hi + WPLANE;
    half* wh_hi = wx_lo + WPLANE;
    half* wh_lo = wh_hi + WPLANE;
    half* stage = wh_lo + WPLANE;                       // NSTAGE * STAGEH
    float* gates_x = (float*)(stage + NSTAGE*STAGEH);   // [MROWS][LDG]
    float* gates_h = gates_x + MROWS*LDG;
    float* c_s     = gates_h + MROWS*LDG;               // [HS*BB]
    float* bias_s  = c_s + HS*BB;                       // [MROWS]

    // ---- Preamble: split weights into fp16 hi/lo (resident all kernel) ----
    const float* WxL = Wxh + (size_t)layer * G4 * HH;
    const float* WhL = Whh + (size_t)layer * G4 * HH;
    for (int i = tid; i < MROWS * HH; i += NTHREADS) {
        int rl = i >> 9;
        int k  = i & (HH - 1);
        int grow = (rl >> 3) * HH + j0 + (rl & 7);
        float wx = WxL[(size_t)grow * HH + k];
        half hx = __float2half_rn(wx);
        wx_hi[rl * LDW + k] = hx;
        wx_lo[rl * LDW + k] = __float2half_rn(wx - __half2float(hx));
        float wh = WhL[(size_t)grow * HH + k];
        half hh2 = __float2half_rn(wh);
        wh_hi[rl * LDW + k] = hh2;
        wh_lo[rl * LDW + k] = __float2half_rn(wh - __half2float(hh2));
    }
    if (tid < MROWS) {
        int grow = (tid >> 3) * HH + j0 + (tid & 7);
        bias_s[tid] = bxh[layer * G4 + grow] + bhh[layer * G4 + grow];
    }
    c_s[tid] = 0.0f;

    // ---- Phase 0: convert x to hi/lo planes once (all CTAs cooperate) ----
    {
        const float4* x4 = (const float4*)x;
        size_t total4 = (size_t)TT * NBH / 4;
        for (size_t i = (size_t)cta * NTHREADS + tid; i < total4; i += (size_t)NCTA * NTHREADS) {
            float4 v = x4[i];
            half a0 = __float2half_rn(v.x), a1 = __float2half_rn(v.y);
            half a2 = __float2half_rn(v.z), a3 = __float2half_rn(v.w);
            half b0 = __float2half_rn(v.x - __half2float(a0));
            half b1 = __float2half_rn(v.y - __half2float(a1));
            half b2 = __float2half_rn(v.z - __half2float(a2));
            half b3 = __float2half_rn(v.w - __half2float(a3));
            ((half2*)g_x_hi)[i*2]   = __halves2half2(a0, a1);
            ((half2*)g_x_hi)[i*2+1] = __halves2half2(a2, a3);
            ((half2*)g_x_lo)[i*2]   = __halves2half2(b0, b1);
            ((half2*)g_x_lo)[i*2+1] = __halves2half2(b2, b3);
        }
    }
    __threadfence();
    __syncthreads();
    if (tid == 0) {
        unsigned old = atomicAdd(&g_gbar_count, 1u);
        if (old == NCTA - 1) { __threadfence(); g_gbar_sense = 1; }
        else { while (g_gbar_sense < 1) { } }
    }
    __syncthreads();

    const int wgrp = (wid < 8) ? 0 : 1;     // 0: x-side GEMM, 1: h-side GEMM
    const int wl   = wid & 7;
    const int m0   = (wl >> 2) * 16;
    const int n0   = (wl & 3) * 16;
    const half* A_hi = wgrp ? wh_hi : wx_hi;
    const half* A_lo = wgrp ? wh_lo : wx_lo;
    const int sOff   = wgrp ? 2*UPLANE : 0;

    // ---- Recurrence ----
    for (int t = 0; t < TT; ++t) {
        const bool has_v = (t > 0);
        const size_t uoff = (size_t)t * NBH;
        const size_t voff = (size_t)(t - 1) * NBH;
        const half *psrc[4];
        if (layer == 0) {
            psrc[0] = g_x_hi + uoff;  psrc[1] = g_x_lo + uoff;
            psrc[2] = g_h0_hi + voff; psrc[3] = g_h0_lo + voff;
        } else {
            psrc[0] = g_h0_hi + uoff; psrc[1] = g_h0_lo + uoff;
            psrc[2] = g_h1_hi + voff; psrc[3] = g_h1_lo + voff;
        }

        // layer 1 waits for layer 0 to publish h0[t]
        if (layer == 1) {
            if (tid == 0) { while (g_sns[0] < t + 1) { } }
            __syncthreads();
            __threadfence();
        }

        const int pend = has_v ? 4 : 2;                       // planes this step
        // chunk-0 planes not yet issued (layer0 pre-issued u planes last step)
        const int pstart = (layer == 0 && t > 0) ? 2 : 0;
        for (int i = tid + pstart*512; i < pend*512; i += NTHREADS) {
            int plane = i >> 9, r = (i >> 3) & 63, s = i & 7;
            __pipeline_memcpy_async(
                stage + plane*UPLANE + r*LDU + s*8,
                psrc[plane] + (size_t)r*HH + s*8, 16);
        }
        __pipeline_commit();

        wmma::fragment<wmma::accumulator, 16, 16, 16, float> acc0, acc1, acc2;
        wmma::fill_fragment(acc0, 0.0f);
        wmma::fill_fragment(acc1, 0.0f);
        wmma::fill_fragment(acc2, 0.0f);
        const bool mywork = (wgrp == 0) || has_v;

        for (int c = 0; c < NCHUNK; ++c) {
            __pipeline_wait_prior(0);
            __syncthreads();
            if (c + 1 < NCHUNK) {
                half* sdst = stage + ((c + 1) & 1) * STAGEH;
                for (int i = tid; i < pend*512; i += NTHREADS) {
                    int plane = i >> 9, r = (i >> 3) & 63, s = i & 7;
                    __pipeline_memcpy_async(
                        sdst + plane*UPLANE + r*LDU + s*8,
                        psrc[plane] + (size_t)r*HH + (c + 1)*KC + s*8, 16);
                }
                __pipeline_commit();
            }
            if (mywork) {
                const half* bbase = stage + (c & 1)*STAGEH + sOff + n0*LDU;
                const half* ahB = A_hi + m0*LDW + c*KC;
                const half* alB = A_lo + m0*LDW + c*KC;
                #pragma unroll
                for (int kk = 0; kk < KC; kk += 16) {
                    wmma::fragment<wmma::matrix_a, 16, 16, 16, half, wmma::row_major> a_hi, a_lo;
                    wmma::fragment<wmma::matrix_b, 16, 16, 16, half, wmma::col_major> b_hi, b_lo;
                    wmma::load_matrix_sync(a_hi, ahB + kk, LDW);
                    wmma::load_matrix_sync(a_lo, alB + kk, LDW);
                    wmma::load_matrix_sync(b_hi, bbase + kk, LDU);
                    wmma::load_matrix_sync(b_lo, bbase + UPLANE + kk, LDU);
                    wmma::mma_sync(acc0, a_hi, b_hi, acc0);
                    wmma::mma_sync(acc1, a_hi, b_lo, acc1);
                    wmma::mma_sync(acc2, a_lo, b_hi, acc2);
                }
            }
        }

        #pragma unroll
        for (int e = 0; e < acc0.num_elements; ++e)
            acc0.x[e] += acc1.x[e] + acc2.x[e];
        float* gbuf = (wgrp == 0) ? gates_x : gates_h;
        wmma::store_matrix_sync(gbuf + m0*LDG + n0, acc0, LDG, wmma::mem_row_major);
        __syncthreads();

        // ---- cell update: one (hidden j, batch b) per thread ----
        {
            int j = tid >> 6;
            int b = tid & 63;
            float ig = gates_x[(j)      * LDG + b] + gates_h[(j)      * LDG + b] + bias_s[j];
            float fg = gates_x[(8 + j)  * LDG + b] + gates_h[(8 + j)  * LDG + b] + bias_s[8 + j];
            float gg = gates_x[(16 + j) * LDG + b] + gates_h[(16 + j) * LDG + b] + bias_s[16 + j];
            float og = gates_x[(24 + j) * LDG + b] + gates_h[(24 + j) * LDG + b] + bias_s[24 + j];
            float cold = c_s[tid];
            float cn = sigf(fg) * cold + sigf(ig) * tanhf(gg);
            c_s[tid] = cn;
            float hv = sigf(og) * tanhf(cn);
            half hhv = __float2half_rn(hv);
            half hlv = __float2half_rn(hv - __half2float(hhv));
            size_t off = (size_t)t * NBH + (size_t)b * HH + j0 + j;
            if (layer == 0) {
                g_h0_hi[off] = hhv; g_h0_lo[off] = hlv;
                if (t == TT - 1) out[HT_OFF + (size_t)b * HH + j0 + j] = hv;
            } else {
                out[off] = hv;
                g_h1_hi[off] = hhv; g_h1_lo[off] = hlv;
                if (t == TT - 1) out[HT_OFF + NBH + (size_t)b * HH + j0 + j] = hv;
            }
        }

        __threadfence();
        __syncthreads();

        // layer 0: pre-issue next step's u planes (x is static) to hide the
        // first L2 round trip behind the barrier spin. stage[0] is free here.
        if (layer == 0 && t + 1 < TT) {
            const half* nuh = g_x_hi + (size_t)(t + 1) * NBH;
            const half* nul = g_x_lo + (size_t)(t + 1) * NBH;
            const half* np[2] = { nuh, nul };
            for (int i = tid; i < 2*512; i += NTHREADS) {
                int plane = i >> 9, r = (i >> 3) & 63, s = i & 7;
                __pipeline_memcpy_async(
                    stage + plane*UPLANE + r*LDU + s*8,
                    np[plane] + (size_t)r*HH + s*8, 16);
            }
        }

        // ---- per-layer 64-CTA barrier; publishes monotonic epoch t+1 ----
        if (tid == 0) {
            unsigned old = atomicAdd(&g_cnt[layer*32], 1u);
            if (old == NCTA_PER_LAYER - 1) {
                g_cnt[layer*32] = 0;
                __threadfence();
                g_sns[layer*32] = t + 1;
            } else {
                while (g_sns[layer*32] < t + 1) { }
            }
        }
        __syncthreads();
    }

    // ---- Tail: cT ----
    {
        int j = tid >> 6;
        int b = tid & 63;
        out[CT_OFF + (size_t)layer * NBH + (size_t)b * HH + j0 + j] = c_s[tid];
    }
}

extern "C" void kernel_launch(void* const* d_in, const int* in_sizes, int n_in,
                              void* d_out, int out_size) {
    const float* x   = (const float*)d_in[0];
    const float* Wxh = (const float*)d_in[1];
    const float* Whh = (const float*)d_in[2];
    const float* bxh = (const float*)d_in[3];
    const float* bhh = (const float*)d_in[4];
    float* out = (float*)d_out;

    reset_kernel<<<1, 1>>>();
    cudaFuncSetAttribute(lstm_persistent_kernel,
                         cudaFuncAttributeMaxDynamicSharedMemorySize, SMEM_BYTES);
    lstm_persistent_kernel<<<NCTA, NTHREADS, SMEM_BYTES>>>(x, Wxh, Whh, bxh, bhh, out);
}